// round 13
// baseline (speedup 1.0000x reference)
#include <cuda_runtime.h>
#include <cuda_bf16.h>
#include <mma.h>
#include <math.h>

using namespace nvcuda;

#define NMAX 100000
#define ESLOTS 1700000   // E + N slack (deg-derived counts over-allocate empty rows)
#define DF   128
#define SCAN_B 1024

// Scratch (__device__ globals; allocation is forbidden).
__device__ float g_agg1[(size_t)NMAX * DF];
__device__ float g_agg2[(size_t)NMAX * DF];
__device__ __align__(16) __nv_bfloat16 g_Wh[3 * 16384];  // row-major [ch][j][k] hi
__device__ __align__(16) __nv_bfloat16 g_Wl[3 * 16384];  // row-major [ch][j][k] lo
__device__ int   g_idx64;
__device__ int   g_cur[NMAX];        // fill cursor (starts at row base)
__device__ int   g_rowptr[NMAX];     // row base (from deg scan)
__device__ int   g_esrc[ESLOTS];
__device__ int   g_sflag[128];       // chained-scan ready flags (zeroed per run)
__device__ int   g_spref[128];       // chained-scan inclusive block prefixes

__device__ __forceinline__ int load_idx(const int* __restrict__ ei32,
                                        long long pos, int idx64) {
    return idx64 ? ei32[2 * pos] : ei32[pos];
}

// ---------------------------------------------------------------------------
// Weights -> bf16 hi/lo, row-major [ch][j][k]. Also: block 0 zeroes the scan
// flags; block 63 detects the edge-index dtype (int64 little-endian has zero
// odd words for values < 2^31).
// ch0: A = s0*W_self + s2*W_hp ; ch1: B = s1*W_nb1 - s2*W_hp ; ch2: C = s3*W_nb2
// ---------------------------------------------------------------------------
__global__ void weight_combine_kernel(const float* __restrict__ Wself,
                                      const float* __restrict__ Wnb1,
                                      const float* __restrict__ Whp,
                                      const float* __restrict__ Wnb2,
                                      const float* __restrict__ logits,
                                      const unsigned* __restrict__ ei_raw,
                                      __nv_bfloat16* __restrict__ Wh,
                                      __nv_bfloat16* __restrict__ Wl) {
    if (blockIdx.x == 0 && threadIdx.x < 128) g_sflag[threadIdx.x] = 0;
    if (blockIdx.x == 63 && threadIdx.x == 0) {
        unsigned acc = 0;
        for (int i = 0; i < 64; i++) acc |= ei_raw[2 * i + 1];
        g_idx64 = (acc == 0u) ? 1 : 0;
    }
    __shared__ float s[4];
    if (threadIdx.x < 4) s[threadIdx.x] = 2.0f / (1.0f + expf(-logits[threadIdx.x]));
    __syncthreads();
    for (int idx = blockIdx.x * blockDim.x + threadIdx.x; idx < DF * DF;
         idx += gridDim.x * blockDim.x) {
        float vals[3];
        vals[0] = s[0] * Wself[idx] + s[2] * Whp[idx];
        vals[1] = s[1] * Wnb1[idx] - s[2] * Whp[idx];
        vals[2] = s[3] * Wnb2[idx];
        for (int ch = 0; ch < 3; ch++) {
            float v = vals[ch];
            __nv_bfloat16 hi = __float2bfloat16_rn(v);
            __nv_bfloat16 lo = __float2bfloat16_rn(v - __bfloat162float(hi));
            Wh[ch * 16384 + idx] = hi;
            Wl[ch * 16384 + idx] = lo;
        }
    }
}

// ---------------------------------------------------------------------------
// Single-kernel chained scan over (int)deg -> rowptr/cur (exclusive bases).
// All 98 blocks are co-resident (98 < 148 SMs), so spinning on the
// predecessor's flag is deadlock-free. deg IS the clamped in-degree
// histogram, so no edge histogram pass is needed.
// ---------------------------------------------------------------------------
__global__ void scan_chain_kernel(const float* __restrict__ deg,
                                  int* __restrict__ rowptr,
                                  int* __restrict__ cur, int n) {
    __shared__ int sh[SCAN_B];
    __shared__ int prevs;
    int tid = threadIdx.x;
    int b = blockIdx.x;
    int i = b * SCAN_B + tid;
    int d = (i < n) ? (int)deg[i] : 0;
    sh[tid] = d;
    __syncthreads();
    for (int o = 1; o < SCAN_B; o <<= 1) {
        int t = (tid >= o) ? sh[tid - o] : 0;
        __syncthreads();
        if (tid >= o) sh[tid] += t;
        __syncthreads();
    }
    if (tid == 0) {
        int prefix = 0;
        if (b > 0) {
            volatile int* vflag = g_sflag;
            while (vflag[b - 1] == 0) {}
            prefix = ((volatile int*)g_spref)[b - 1];
        }
        g_spref[b] = prefix + sh[SCAN_B - 1];
        __threadfence();
        atomicExch(&g_sflag[b], 1);
        prevs = prefix;
    }
    __syncthreads();
    if (i < n) {
        int base = sh[tid] + prevs - d;
        rowptr[i] = base;
        cur[i] = base;
    }
}

__global__ void fill_kernel(const int* __restrict__ ei32,
                            int* __restrict__ cur, int* __restrict__ esrc,
                            long long E) {
    long long e = (long long)blockIdx.x * blockDim.x + threadIdx.x;
    if (e >= E) return;
    int idx64 = g_idx64;
    int src = load_idx(ei32, e, idx64);
    int dst = load_idx(ei32, e + E, idx64);
    int pos = atomicAdd(&cur[dst], 1);
    esrc[pos] = src;
}

// ---------------------------------------------------------------------------
// Gather-based mean aggregation: warp per node, lane owns one float4.
// Range = [rowptr[w], cur[w]) : cur is the post-fill cursor (= base + count).
// ---------------------------------------------------------------------------
__global__ __launch_bounds__(256) void agg_gather_kernel(
    const int* __restrict__ rowptr, const int* __restrict__ rowend,
    const int* __restrict__ esrc,
    const float4* __restrict__ x4, float4* __restrict__ out4,
    const float* __restrict__ deg, int Nn) {
    int w = (blockIdx.x * blockDim.x + threadIdx.x) >> 5;
    if (w >= Nn) return;
    int lane = threadIdx.x & 31;
    int s = rowptr[w];
    int t = rowend[w];
    float4 a = make_float4(0.f, 0.f, 0.f, 0.f);
    int j = s;
    for (; j + 8 <= t; j += 8) {
        int si[8];
#pragma unroll
        for (int u = 0; u < 8; u++) si[u] = esrc[j + u];
        float4 v[8];
#pragma unroll
        for (int u = 0; u < 8; u++) v[u] = x4[(long long)si[u] * 32 + lane];
        float4 p0, p1;
        p0.x = (v[0].x + v[1].x) + (v[2].x + v[3].x);
        p0.y = (v[0].y + v[1].y) + (v[2].y + v[3].y);
        p0.z = (v[0].z + v[1].z) + (v[2].z + v[3].z);
        p0.w = (v[0].w + v[1].w) + (v[2].w + v[3].w);
        p1.x = (v[4].x + v[5].x) + (v[6].x + v[7].x);
        p1.y = (v[4].y + v[5].y) + (v[6].y + v[7].y);
        p1.z = (v[4].z + v[5].z) + (v[6].z + v[7].z);
        p1.w = (v[4].w + v[5].w) + (v[6].w + v[7].w);
        a.x += p0.x + p1.x;
        a.y += p0.y + p1.y;
        a.z += p0.z + p1.z;
        a.w += p0.w + p1.w;
    }
    for (; j < t; j++) {
        int s0 = esrc[j];
        float4 v = x4[(long long)s0 * 32 + lane];
        a.x += v.x;
        a.y += v.y;
        a.z += v.z;
        a.w += v.w;
    }
    float rd = 1.0f / deg[w];
    a.x *= rd;
    a.y *= rd;
    a.z *= rd;
    a.w *= rd;
    out4[(long long)w * 32 + lane] = a;
}

// ---------------------------------------------------------------------------
// WMMA GEMM (CTA: 64 rows x 128 cols, K=384 as 3 chunks of 128) + bias + LN.
// 3-term bf16 split: Xh*Wh + Xh*Wl + Xl*Wh, fp32 accumulators.
// 8 warps; warp tile 32x32 (2x2 of 16x16 fragments). B loaded from GLOBAL
// (W images are L1/L2-resident). smem = 36,864 B -> 2 CTAs/SM.
// [round-11 configuration: fastest measured]
// ---------------------------------------------------------------------------
#define BMR 64    // CTA rows
#define LDX 144   // bf16 elements per row in X stage (288B rows, 32B aligned)
#define LDZ 132   // floats per row in Z epilogue tile

__global__ __launch_bounds__(256) void wmma_gemm_ln_kernel(
    const float* __restrict__ h, const float* __restrict__ nb1,
    const float* __restrict__ nb2,
    const __nv_bfloat16* __restrict__ Wh,
    const __nv_bfloat16* __restrict__ Wl,
    const float* __restrict__ bias, const float* __restrict__ gamma,
    const float* __restrict__ beta, float* __restrict__ out, int Nn) {
    extern __shared__ __align__(32) char sm[];
    __nv_bfloat16* Xh_s = (__nv_bfloat16*)sm;                 // 64*144*2 = 18,432
    __nv_bfloat16* Xl_s = (__nv_bfloat16*)(sm + 18432);       // 18,432 (total 36,864)
    float* Z = (float*)sm;                                    // 64*132*4 (aliases X)

    __shared__ float bias_s[128];
    __shared__ float gamma_s[128];
    __shared__ float beta_s[128];
    __shared__ float mean_s[BMR];
    __shared__ float inv_s[BMR];

    int tid = threadIdx.x;
    int wid = tid >> 5;
    int row0 = blockIdx.x * BMR;
    int warp_row = wid >> 2;        // 0..1 -> rows warp_row*32
    int warp_col = wid & 3;         // 0..3 -> cols warp_col*32

    if (tid < 128) {
        bias_s[tid] = bias[tid];
        gamma_s[tid] = gamma[tid];
        beta_s[tid] = beta[tid];
    }

    wmma::fragment<wmma::accumulator, 16, 16, 16, float> acc[2][2];
    for (int i = 0; i < 2; i++)
        for (int j = 0; j < 2; j++)
            wmma::fill_fragment(acc[i][j], 0.0f);

    const float* srcs[3];
    srcs[0] = h;
    srcs[1] = nb1;
    srcs[2] = nb2;

    for (int ch = 0; ch < 3; ch++) {
        const float* S = srcs[ch];
        const __nv_bfloat16* WhC = Wh + ch * 16384;
        const __nv_bfloat16* WlC = Wl + ch * 16384;
        __syncthreads();   // previous chunk's consumers done before overwrite

        // Stage X: 64 rows x 128 cols fp32 -> bf16 hi/lo (2048 float4 loads).
        for (int it = 0; it < 8; it++) {
            int idx = it * 256 + tid;
            int row = idx >> 5;
            int col = (idx & 31) * 4;
            float4 v = make_float4(0.f, 0.f, 0.f, 0.f);
            int gr = row0 + row;
            if (gr < Nn) v = *(const float4*)(S + (long long)gr * DF + col);
            __nv_bfloat16 hx = __float2bfloat16_rn(v.x);
            __nv_bfloat16 hy = __float2bfloat16_rn(v.y);
            __nv_bfloat16 hz = __float2bfloat16_rn(v.z);
            __nv_bfloat16 hw = __float2bfloat16_rn(v.w);
            __nv_bfloat16 lx = __float2bfloat16_rn(v.x - __bfloat162float(hx));
            __nv_bfloat16 ly = __float2bfloat16_rn(v.y - __bfloat162float(hy));
            __nv_bfloat16 lz = __float2bfloat16_rn(v.z - __bfloat162float(hz));
            __nv_bfloat16 lw = __float2bfloat16_rn(v.w - __bfloat162float(hw));
            uint2 hv;
            uint2 lv;
            hv.x = (unsigned)__bfloat16_as_ushort(hx)
                 | ((unsigned)__bfloat16_as_ushort(hy) << 16);
            hv.y = (unsigned)__bfloat16_as_ushort(hz)
                 | ((unsigned)__bfloat16_as_ushort(hw) << 16);
            lv.x = (unsigned)__bfloat16_as_ushort(lx)
                 | ((unsigned)__bfloat16_as_ushort(ly) << 16);
            lv.y = (unsigned)__bfloat16_as_ushort(lz)
                 | ((unsigned)__bfloat16_as_ushort(lw) << 16);
            *(uint2*)(Xh_s + row * LDX + col) = hv;
            *(uint2*)(Xl_s + row * LDX + col) = lv;
        }
        __syncthreads();

        // MMA over this chunk's K=128. B fragments read straight from global.
        for (int ks = 0; ks < 8; ks++) {
            int k0 = ks * 16;
            wmma::fragment<wmma::matrix_a, 16, 16, 16, __nv_bfloat16, wmma::row_major> ah[2], al[2];
            for (int i = 0; i < 2; i++) {
                int r = warp_row * 32 + i * 16;
                wmma::load_matrix_sync(ah[i], Xh_s + r * LDX + k0, LDX);
                wmma::load_matrix_sync(al[i], Xl_s + r * LDX + k0, LDX);
            }
            for (int j = 0; j < 2; j++) {
                int c = warp_col * 32 + j * 16;
                wmma::fragment<wmma::matrix_b, 16, 16, 16, __nv_bfloat16, wmma::col_major> bh, bl;
                wmma::load_matrix_sync(bh, WhC + c * 128 + k0, 128);
                wmma::load_matrix_sync(bl, WlC + c * 128 + k0, 128);
                for (int i = 0; i < 2; i++) {
                    wmma::mma_sync(acc[i][j], ah[i], bh, acc[i][j]);
                    wmma::mma_sync(acc[i][j], ah[i], bl, acc[i][j]);
                    wmma::mma_sync(acc[i][j], al[i], bh, acc[i][j]);
                }
            }
        }
    }
    __syncthreads();   // all MMA consumers done; Z aliases X stage

    // Store accumulators to Z
    for (int i = 0; i < 2; i++) {
        for (int j = 0; j < 2; j++) {
            int r = warp_row * 32 + i * 16;
            int c = warp_col * 32 + j * 16;
            wmma::store_matrix_sync(Z + r * LDZ + c, acc[i][j], LDZ, wmma::mem_row_major);
        }
    }
    __syncthreads();

    // LayerNorm stats: 4 threads per row, 32 cols each; add bias in-place.
    {
        int row = tid >> 2;
        int q = tid & 3;
        float sum = 0.f;
        float sq = 0.f;
        for (int c = 0; c < 32; c++) {
            int col = q * 32 + c;
            float z = Z[row * LDZ + col] + bias_s[col];
            Z[row * LDZ + col] = z;
            sum += z;
            sq += z * z;
        }
        sum += __shfl_xor_sync(0xffffffffu, sum, 1);
        sq += __shfl_xor_sync(0xffffffffu, sq, 1);
        sum += __shfl_xor_sync(0xffffffffu, sum, 2);
        sq += __shfl_xor_sync(0xffffffffu, sq, 2);
        if (q == 0) {
            float mean = sum * (1.0f / 128.0f);
            float var = sq * (1.0f / 128.0f) - mean * mean;
            mean_s[row] = mean;
            inv_s[row] = rsqrtf(var + 1e-5f);
        }
    }
    __syncthreads();

    // Coalesced normalize + store: 8 iters x 256 threads x float4
    for (int it = 0; it < 8; it++) {
        int g = it * 1024 + tid * 4;
        int row = g >> 7;
        int col = g & 127;
        int gr = row0 + row;
        if (gr < Nn) {
            float m = mean_s[row];
            float iv = inv_s[row];
            float4 o;
            o.x = (Z[row * LDZ + col + 0] - m) * iv * gamma_s[col + 0] + beta_s[col + 0];
            o.y = (Z[row * LDZ + col + 1] - m) * iv * gamma_s[col + 1] + beta_s[col + 1];
            o.z = (Z[row * LDZ + col + 2] - m) * iv * gamma_s[col + 2] + beta_s[col + 2];
            o.w = (Z[row * LDZ + col + 3] - m) * iv * gamma_s[col + 3] + beta_s[col + 3];
            *(float4*)(out + (long long)gr * DF + col) = o;
        }
    }
}

// ---------------------------------------------------------------------------
// Launch
// ---------------------------------------------------------------------------
extern "C" void kernel_launch(void* const* d_in, const int* in_sizes, int n_in,
                              void* d_out, int out_size) {
    const float* h      = (const float*)d_in[0];
    const int*   ei32   = (const int*)d_in[1];
    const float* deg    = (const float*)d_in[2];
    const float* Wself  = (const float*)d_in[3];
    const float* Wnb1   = (const float*)d_in[4];
    const float* Whp    = (const float*)d_in[5];
    const float* Wnb2   = (const float*)d_in[6];
    const float* bias   = (const float*)d_in[7];
    const float* logits = (const float*)d_in[8];
    const float* gamma  = (const float*)d_in[9];
    const float* beta   = (const float*)d_in[10];
    float*       out    = (float*)d_out;

    int Nn = in_sizes[2];
    long long E = in_sizes[1] / 2;

    float* agg1;
    float* agg2;
    __nv_bfloat16* Wh;
    __nv_bfloat16* Wl;
    int* cur;
    int* rowptr;
    int* esrc;
    cudaGetSymbolAddress((void**)&agg1, g_agg1);
    cudaGetSymbolAddress((void**)&agg2, g_agg2);
    cudaGetSymbolAddress((void**)&Wh, g_Wh);
    cudaGetSymbolAddress((void**)&Wl, g_Wl);
    cudaGetSymbolAddress((void**)&cur, g_cur);
    cudaGetSymbolAddress((void**)&rowptr, g_rowptr);
    cudaGetSymbolAddress((void**)&esrc, g_esrc);

    const int T = 256;
    int nb_edges = (int)((E + T - 1) / T);
    int nb_scan  = (Nn + SCAN_B - 1) / SCAN_B;
    int nb_agg   = (Nn * 32 + T - 1) / T;
    int fb       = (Nn + BMR - 1) / BMR;
    const int GEMM_SMEM = 36864;   // Xh + Xl stage (Z epilogue aliases it)

    cudaFuncSetAttribute(wmma_gemm_ln_kernel,
                         cudaFuncAttributeMaxDynamicSharedMemorySize, GEMM_SMEM);

    // 1) weights + scan-flag zeroing + index-dtype detect (one kernel)
    weight_combine_kernel<<<64, T>>>(Wself, Wnb1, Whp, Wnb2, logits,
                                     (const unsigned*)ei32, Wh, Wl);
    // 2) CSR row bases from deg via single-kernel chained scan
    scan_chain_kernel<<<nb_scan, SCAN_B>>>(deg, rowptr, cur, Nn);
    // 3) adjacency fill (cursor ends at row base + count)
    fill_kernel<<<nb_edges, T>>>(ei32, cur, esrc, E);
    // 4) nb1 = mean-gather(h); nb2 = mean-gather(nb1)
    agg_gather_kernel<<<nb_agg, T>>>(rowptr, cur, esrc, (const float4*)h,
                                     (float4*)agg1, deg, Nn);
    agg_gather_kernel<<<nb_agg, T>>>(rowptr, cur, esrc, (const float4*)agg1,
                                     (float4*)agg2, deg, Nn);
    // 5) fused GEMM + bias + LayerNorm
    wmma_gemm_ln_kernel<<<fb, 256, GEMM_SMEM>>>(h, agg1, agg2, Wh, Wl,
                                                bias, gamma, beta, out, Nn);
}

// round 14
// speedup vs baseline: 1.2325x; 1.2325x over previous
#include <cuda_runtime.h>
#include <cuda_bf16.h>
#include <mma.h>
#include <math.h>

using namespace nvcuda;

#define NMAX 100000
#define ESLOTS 1700000   // E + N slack (deg-derived counts over-allocate empty rows)
#define DF   128
#define SCAN_B 1024

// Scratch (__device__ globals; allocation is forbidden).
__device__ float g_agg1[(size_t)NMAX * DF];
__device__ float g_agg2[(size_t)NMAX * DF];
__device__ __align__(16) __nv_bfloat16 g_Wh[3 * 16384];  // row-major [ch][j][k] hi
__device__ __align__(16) __nv_bfloat16 g_Wl[3 * 16384];  // row-major [ch][j][k] lo
__device__ int   g_idx64;
__device__ int   g_cur[NMAX];        // fill cursor (starts at row base)
__device__ int   g_scan[NMAX];
__device__ int   g_bsum[1024];
__device__ int   g_rowptr[NMAX];     // row base (from deg scan)
__device__ int   g_esrc[ESLOTS];

__device__ __forceinline__ int load_idx(const int* __restrict__ ei32,
                                        long long pos, int idx64) {
    return idx64 ? ei32[2 * pos] : ei32[pos];
}

// ---------------------------------------------------------------------------
// Weights -> bf16 hi/lo, row-major [ch][j][k]. Block 63 also detects the
// edge-index dtype (int64 little-endian has zero odd words for v < 2^31).
// ch0: A = s0*W_self + s2*W_hp ; ch1: B = s1*W_nb1 - s2*W_hp ; ch2: C = s3*W_nb2
// ---------------------------------------------------------------------------
__global__ void weight_combine_kernel(const float* __restrict__ Wself,
                                      const float* __restrict__ Wnb1,
                                      const float* __restrict__ Whp,
                                      const float* __restrict__ Wnb2,
                                      const float* __restrict__ logits,
                                      const unsigned* __restrict__ ei_raw,
                                      __nv_bfloat16* __restrict__ Wh,
                                      __nv_bfloat16* __restrict__ Wl) {
    if (blockIdx.x == 63 && threadIdx.x == 0) {
        unsigned acc = 0;
        for (int i = 0; i < 64; i++) acc |= ei_raw[2 * i + 1];
        g_idx64 = (acc == 0u) ? 1 : 0;
    }
    __shared__ float s[4];
    if (threadIdx.x < 4) s[threadIdx.x] = 2.0f / (1.0f + expf(-logits[threadIdx.x]));
    __syncthreads();
    for (int idx = blockIdx.x * blockDim.x + threadIdx.x; idx < DF * DF;
         idx += gridDim.x * blockDim.x) {
        float vals[3];
        vals[0] = s[0] * Wself[idx] + s[2] * Whp[idx];
        vals[1] = s[1] * Wnb1[idx] - s[2] * Whp[idx];
        vals[2] = s[3] * Wnb2[idx];
        for (int ch = 0; ch < 3; ch++) {
            float v = vals[ch];
            __nv_bfloat16 hi = __float2bfloat16_rn(v);
            __nv_bfloat16 lo = __float2bfloat16_rn(v - __bfloat162float(hi));
            Wh[ch * 16384 + idx] = hi;
            Wl[ch * 16384 + idx] = lo;
        }
    }
}

// ---------------------------------------------------------------------------
// CSR build from deg (deg IS the clamped in-degree histogram -> no hist pass).
// Three-phase parallel scan (measured ~10 us total; chained version regressed).
// ---------------------------------------------------------------------------
__global__ void scan_a_kernel(const float* __restrict__ deg, int* __restrict__ scan,
                              int* __restrict__ bsum, int n) {
    __shared__ int sh[SCAN_B];
    int tid = threadIdx.x;
    int i = blockIdx.x * SCAN_B + tid;
    sh[tid] = (i < n) ? (int)deg[i] : 0;
    __syncthreads();
    for (int o = 1; o < SCAN_B; o <<= 1) {
        int t = (tid >= o) ? sh[tid - o] : 0;
        __syncthreads();
        if (tid >= o) sh[tid] += t;
        __syncthreads();
    }
    if (i < n) scan[i] = sh[tid];
    if (tid == SCAN_B - 1) bsum[blockIdx.x] = sh[tid];
}

__global__ void scan_b_kernel(int* __restrict__ bsum, int nb) {
    __shared__ int sh[1024];
    int tid = threadIdx.x;
    int v = (tid < nb) ? bsum[tid] : 0;
    sh[tid] = v;
    __syncthreads();
    for (int o = 1; o < 1024; o <<= 1) {
        int t = (tid >= o) ? sh[tid - o] : 0;
        __syncthreads();
        if (tid >= o) sh[tid] += t;
        __syncthreads();
    }
    if (tid < nb) bsum[tid] = sh[tid] - v;
}

__global__ void scan_c_kernel(const int* __restrict__ scan,
                              const int* __restrict__ bsum,
                              const float* __restrict__ deg,
                              int* __restrict__ rowptr, int* __restrict__ cur, int n) {
    int i = blockIdx.x * blockDim.x + threadIdx.x;
    if (i < n) {
        int incl = scan[i] + bsum[i / SCAN_B];
        int base = incl - (int)deg[i];
        rowptr[i] = base;
        cur[i] = base;
    }
}

__global__ void fill_kernel(const int* __restrict__ ei32,
                            int* __restrict__ cur, int* __restrict__ esrc,
                            long long E) {
    long long e = (long long)blockIdx.x * blockDim.x + threadIdx.x;
    if (e >= E) return;
    int idx64 = g_idx64;
    int src = load_idx(ei32, e, idx64);
    int dst = load_idx(ei32, e + E, idx64);
    int pos = atomicAdd(&cur[dst], 1);
    esrc[pos] = src;
}

// ---------------------------------------------------------------------------
// Gather-based mean aggregation: warp per node, lane owns one float4.
// Range = [rowptr[w], cur[w]) : cur is the post-fill cursor (= base + count).
// ---------------------------------------------------------------------------
__global__ __launch_bounds__(256) void agg_gather_kernel(
    const int* __restrict__ rowptr, const int* __restrict__ rowend,
    const int* __restrict__ esrc,
    const float4* __restrict__ x4, float4* __restrict__ out4,
    const float* __restrict__ deg, int Nn) {
    int w = (blockIdx.x * blockDim.x + threadIdx.x) >> 5;
    if (w >= Nn) return;
    int lane = threadIdx.x & 31;
    int s = rowptr[w];
    int t = rowend[w];
    float4 a = make_float4(0.f, 0.f, 0.f, 0.f);
    int j = s;
    for (; j + 8 <= t; j += 8) {
        int si[8];
#pragma unroll
        for (int u = 0; u < 8; u++) si[u] = esrc[j + u];
        float4 v[8];
#pragma unroll
        for (int u = 0; u < 8; u++) v[u] = x4[(long long)si[u] * 32 + lane];
        float4 p0, p1;
        p0.x = (v[0].x + v[1].x) + (v[2].x + v[3].x);
        p0.y = (v[0].y + v[1].y) + (v[2].y + v[3].y);
        p0.z = (v[0].z + v[1].z) + (v[2].z + v[3].z);
        p0.w = (v[0].w + v[1].w) + (v[2].w + v[3].w);
        p1.x = (v[4].x + v[5].x) + (v[6].x + v[7].x);
        p1.y = (v[4].y + v[5].y) + (v[6].y + v[7].y);
        p1.z = (v[4].z + v[5].z) + (v[6].z + v[7].z);
        p1.w = (v[4].w + v[5].w) + (v[6].w + v[7].w);
        a.x += p0.x + p1.x;
        a.y += p0.y + p1.y;
        a.z += p0.z + p1.z;
        a.w += p0.w + p1.w;
    }
    for (; j < t; j++) {
        int s0 = esrc[j];
        float4 v = x4[(long long)s0 * 32 + lane];
        a.x += v.x;
        a.y += v.y;
        a.z += v.z;
        a.w += v.w;
    }
    float rd = 1.0f / deg[w];
    a.x *= rd;
    a.y *= rd;
    a.z *= rd;
    a.w *= rd;
    out4[(long long)w * 32 + lane] = a;
}

// ---------------------------------------------------------------------------
// WMMA GEMM (CTA: 64 rows x 128 cols, K=384 as 3 chunks of 128) + bias + LN.
// 3-term bf16 split: Xh*Wh + Xh*Wl + Xl*Wh, fp32 accumulators.
// 8 warps; warp tile 32x32 (2x2 of 16x16 fragments). B loaded from GLOBAL
// (W images are L1/L2-resident). smem = 36,864 B -> 2 CTAs/SM.
// [round-11 configuration: fastest measured]
// ---------------------------------------------------------------------------
#define BMR 64    // CTA rows
#define LDX 144   // bf16 elements per row in X stage (288B rows, 32B aligned)
#define LDZ 132   // floats per row in Z epilogue tile

__global__ __launch_bounds__(256) void wmma_gemm_ln_kernel(
    const float* __restrict__ h, const float* __restrict__ nb1,
    const float* __restrict__ nb2,
    const __nv_bfloat16* __restrict__ Wh,
    const __nv_bfloat16* __restrict__ Wl,
    const float* __restrict__ bias, const float* __restrict__ gamma,
    const float* __restrict__ beta, float* __restrict__ out, int Nn) {
    extern __shared__ __align__(32) char sm[];
    __nv_bfloat16* Xh_s = (__nv_bfloat16*)sm;                 // 64*144*2 = 18,432
    __nv_bfloat16* Xl_s = (__nv_bfloat16*)(sm + 18432);       // 18,432 (total 36,864)
    float* Z = (float*)sm;                                    // 64*132*4 (aliases X)

    __shared__ float bias_s[128];
    __shared__ float gamma_s[128];
    __shared__ float beta_s[128];
    __shared__ float mean_s[BMR];
    __shared__ float inv_s[BMR];

    int tid = threadIdx.x;
    int wid = tid >> 5;
    int row0 = blockIdx.x * BMR;
    int warp_row = wid >> 2;        // 0..1 -> rows warp_row*32
    int warp_col = wid & 3;         // 0..3 -> cols warp_col*32

    if (tid < 128) {
        bias_s[tid] = bias[tid];
        gamma_s[tid] = gamma[tid];
        beta_s[tid] = beta[tid];
    }

    wmma::fragment<wmma::accumulator, 16, 16, 16, float> acc[2][2];
    for (int i = 0; i < 2; i++)
        for (int j = 0; j < 2; j++)
            wmma::fill_fragment(acc[i][j], 0.0f);

    const float* srcs[3];
    srcs[0] = h;
    srcs[1] = nb1;
    srcs[2] = nb2;

    for (int ch = 0; ch < 3; ch++) {
        const float* S = srcs[ch];
        const __nv_bfloat16* WhC = Wh + ch * 16384;
        const __nv_bfloat16* WlC = Wl + ch * 16384;
        __syncthreads();   // previous chunk's consumers done before overwrite

        // Stage X: 64 rows x 128 cols fp32 -> bf16 hi/lo (2048 float4 loads).
        for (int it = 0; it < 8; it++) {
            int idx = it * 256 + tid;
            int row = idx >> 5;
            int col = (idx & 31) * 4;
            float4 v = make_float4(0.f, 0.f, 0.f, 0.f);
            int gr = row0 + row;
            if (gr < Nn) v = *(const float4*)(S + (long long)gr * DF + col);
            __nv_bfloat16 hx = __float2bfloat16_rn(v.x);
            __nv_bfloat16 hy = __float2bfloat16_rn(v.y);
            __nv_bfloat16 hz = __float2bfloat16_rn(v.z);
            __nv_bfloat16 hw = __float2bfloat16_rn(v.w);
            __nv_bfloat16 lx = __float2bfloat16_rn(v.x - __bfloat162float(hx));
            __nv_bfloat16 ly = __float2bfloat16_rn(v.y - __bfloat162float(hy));
            __nv_bfloat16 lz = __float2bfloat16_rn(v.z - __bfloat162float(hz));
            __nv_bfloat16 lw = __float2bfloat16_rn(v.w - __bfloat162float(hw));
            uint2 hv;
            uint2 lv;
            hv.x = (unsigned)__bfloat16_as_ushort(hx)
                 | ((unsigned)__bfloat16_as_ushort(hy) << 16);
            hv.y = (unsigned)__bfloat16_as_ushort(hz)
                 | ((unsigned)__bfloat16_as_ushort(hw) << 16);
            lv.x = (unsigned)__bfloat16_as_ushort(lx)
                 | ((unsigned)__bfloat16_as_ushort(ly) << 16);
            lv.y = (unsigned)__bfloat16_as_ushort(lz)
                 | ((unsigned)__bfloat16_as_ushort(lw) << 16);
            *(uint2*)(Xh_s + row * LDX + col) = hv;
            *(uint2*)(Xl_s + row * LDX + col) = lv;
        }
        __syncthreads();

        // MMA over this chunk's K=128. B fragments read straight from global.
        for (int ks = 0; ks < 8; ks++) {
            int k0 = ks * 16;
            wmma::fragment<wmma::matrix_a, 16, 16, 16, __nv_bfloat16, wmma::row_major> ah[2], al[2];
            for (int i = 0; i < 2; i++) {
                int r = warp_row * 32 + i * 16;
                wmma::load_matrix_sync(ah[i], Xh_s + r * LDX + k0, LDX);
                wmma::load_matrix_sync(al[i], Xl_s + r * LDX + k0, LDX);
            }
            for (int j = 0; j < 2; j++) {
                int c = warp_col * 32 + j * 16;
                wmma::fragment<wmma::matrix_b, 16, 16, 16, __nv_bfloat16, wmma::col_major> bh, bl;
                wmma::load_matrix_sync(bh, WhC + c * 128 + k0, 128);
                wmma::load_matrix_sync(bl, WlC + c * 128 + k0, 128);
                for (int i = 0; i < 2; i++) {
                    wmma::mma_sync(acc[i][j], ah[i], bh, acc[i][j]);
                    wmma::mma_sync(acc[i][j], ah[i], bl, acc[i][j]);
                    wmma::mma_sync(acc[i][j], al[i], bh, acc[i][j]);
                }
            }
        }
    }
    __syncthreads();   // all MMA consumers done; Z aliases X stage

    // Store accumulators to Z
    for (int i = 0; i < 2; i++) {
        for (int j = 0; j < 2; j++) {
            int r = warp_row * 32 + i * 16;
            int c = warp_col * 32 + j * 16;
            wmma::store_matrix_sync(Z + r * LDZ + c, acc[i][j], LDZ, wmma::mem_row_major);
        }
    }
    __syncthreads();

    // LayerNorm stats: 4 threads per row, 32 cols each; add bias in-place.
    {
        int row = tid >> 2;
        int q = tid & 3;
        float sum = 0.f;
        float sq = 0.f;
        for (int c = 0; c < 32; c++) {
            int col = q * 32 + c;
            float z = Z[row * LDZ + col] + bias_s[col];
            Z[row * LDZ + col] = z;
            sum += z;
            sq += z * z;
        }
        sum += __shfl_xor_sync(0xffffffffu, sum, 1);
        sq += __shfl_xor_sync(0xffffffffu, sq, 1);
        sum += __shfl_xor_sync(0xffffffffu, sum, 2);
        sq += __shfl_xor_sync(0xffffffffu, sq, 2);
        if (q == 0) {
            float mean = sum * (1.0f / 128.0f);
            float var = sq * (1.0f / 128.0f) - mean * mean;
            mean_s[row] = mean;
            inv_s[row] = rsqrtf(var + 1e-5f);
        }
    }
    __syncthreads();

    // Coalesced normalize + store: 8 iters x 256 threads x float4
    for (int it = 0; it < 8; it++) {
        int g = it * 1024 + tid * 4;
        int row = g >> 7;
        int col = g & 127;
        int gr = row0 + row;
        if (gr < Nn) {
            float m = mean_s[row];
            float iv = inv_s[row];
            float4 o;
            o.x = (Z[row * LDZ + col + 0] - m) * iv * gamma_s[col + 0] + beta_s[col + 0];
            o.y = (Z[row * LDZ + col + 1] - m) * iv * gamma_s[col + 1] + beta_s[col + 1];
            o.z = (Z[row * LDZ + col + 2] - m) * iv * gamma_s[col + 2] + beta_s[col + 2];
            o.w = (Z[row * LDZ + col + 3] - m) * iv * gamma_s[col + 3] + beta_s[col + 3];
            *(float4*)(out + (long long)gr * DF + col) = o;
        }
    }
}

// ---------------------------------------------------------------------------
// Launch
// ---------------------------------------------------------------------------
extern "C" void kernel_launch(void* const* d_in, const int* in_sizes, int n_in,
                              void* d_out, int out_size) {
    const float* h      = (const float*)d_in[0];
    const int*   ei32   = (const int*)d_in[1];
    const float* deg    = (const float*)d_in[2];
    const float* Wself  = (const float*)d_in[3];
    const float* Wnb1   = (const float*)d_in[4];
    const float* Whp    = (const float*)d_in[5];
    const float* Wnb2   = (const float*)d_in[6];
    const float* bias   = (const float*)d_in[7];
    const float* logits = (const float*)d_in[8];
    const float* gamma  = (const float*)d_in[9];
    const float* beta   = (const float*)d_in[10];
    float*       out    = (float*)d_out;

    int Nn = in_sizes[2];
    long long E = in_sizes[1] / 2;

    float* agg1;
    float* agg2;
    __nv_bfloat16* Wh;
    __nv_bfloat16* Wl;
    int* cur;
    int* scan;
    int* bsum;
    int* rowptr;
    int* esrc;
    cudaGetSymbolAddress((void**)&agg1, g_agg1);
    cudaGetSymbolAddress((void**)&agg2, g_agg2);
    cudaGetSymbolAddress((void**)&Wh, g_Wh);
    cudaGetSymbolAddress((void**)&Wl, g_Wl);
    cudaGetSymbolAddress((void**)&cur, g_cur);
    cudaGetSymbolAddress((void**)&scan, g_scan);
    cudaGetSymbolAddress((void**)&bsum, g_bsum);
    cudaGetSymbolAddress((void**)&rowptr, g_rowptr);
    cudaGetSymbolAddress((void**)&esrc, g_esrc);

    const int T = 256;
    int nb_nodes = (Nn + T - 1) / T;
    int nb_edges = (int)((E + T - 1) / T);
    int nb_scan  = (Nn + SCAN_B - 1) / SCAN_B;
    int nb_agg   = (Nn * 32 + T - 1) / T;
    int fb       = (Nn + BMR - 1) / BMR;
    const int GEMM_SMEM = 36864;   // Xh + Xl stage (Z epilogue aliases it)

    cudaFuncSetAttribute(wmma_gemm_ln_kernel,
                         cudaFuncAttributeMaxDynamicSharedMemorySize, GEMM_SMEM);

    // 1) weights + index-dtype detect (one kernel; completes before fill)
    weight_combine_kernel<<<64, T>>>(Wself, Wnb1, Whp, Wnb2, logits,
                                     (const unsigned*)ei32, Wh, Wl);
    // 2) CSR row bases from deg (three-phase parallel scan)
    scan_a_kernel<<<nb_scan, SCAN_B>>>(deg, scan, bsum, Nn);
    scan_b_kernel<<<1, 1024>>>(bsum, nb_scan);
    scan_c_kernel<<<nb_nodes, T>>>(scan, bsum, deg, rowptr, cur, Nn);
    // 3) adjacency fill (cursor ends at row base + count)
    fill_kernel<<<nb_edges, T>>>(ei32, cur, esrc, E);
    // 4) nb1 = mean-gather(h); nb2 = mean-gather(nb1)
    agg_gather_kernel<<<nb_agg, T>>>(rowptr, cur, esrc, (const float4*)h,
                                     (float4*)agg1, deg, Nn);
    agg_gather_kernel<<<nb_agg, T>>>(rowptr, cur, esrc, (const float4*)agg1,
                                     (float4*)agg2, deg, Nn);
    // 5) fused GEMM + bias + LayerNorm
    wmma_gemm_ln_kernel<<<fb, 256, GEMM_SMEM>>>(h, agg1, agg2, Wh, Wl,
                                                bias, gamma, beta, out, Nn);
}

// round 16
// speedup vs baseline: 1.3469x; 1.0928x over previous
#include <cuda_runtime.h>
#include <cuda_bf16.h>
#include <mma.h>
#include <math.h>

using namespace nvcuda;

#define NMAX 100000
#define ESLOTS 1700000   // E + N slack (deg-derived counts over-allocate empty rows)
#define DF   128
#define SCAN_B 1024

// Scratch (__device__ globals; allocation is forbidden).
__device__ float g_agg1[(size_t)NMAX * DF];
__device__ float g_agg2[(size_t)NMAX * DF];
__device__ __align__(16) __nv_bfloat16 g_Wh[3 * 16384];  // row-major [ch][j][k] hi
__device__ __align__(16) __nv_bfloat16 g_Wl[3 * 16384];  // row-major [ch][j][k] lo
__device__ int   g_idx64;
__device__ int   g_cur[NMAX];        // fill cursor (starts at row base)
__device__ int   g_scan[NMAX];
__device__ int   g_bsum[1024];
__device__ int   g_rowptr[NMAX];     // row base (from deg scan)
__device__ int   g_esrc[ESLOTS];

__device__ __forceinline__ int load_idx(const int* __restrict__ ei32,
                                        long long pos, int idx64) {
    return idx64 ? ei32[2 * pos] : ei32[pos];
}

// ---------------------------------------------------------------------------
// Weights -> bf16 hi/lo, row-major [ch][j][k]. Block 63 also detects the
// edge-index dtype (int64 little-endian has zero odd words for v < 2^31).
// ch0: A = s0*W_self + s2*W_hp ; ch1: B = s1*W_nb1 - s2*W_hp ; ch2: C = s3*W_nb2
// ---------------------------------------------------------------------------
__global__ void weight_combine_kernel(const float* __restrict__ Wself,
                                      const float* __restrict__ Wnb1,
                                      const float* __restrict__ Whp,
                                      const float* __restrict__ Wnb2,
                                      const float* __restrict__ logits,
                                      const unsigned* __restrict__ ei_raw,
                                      __nv_bfloat16* __restrict__ Wh,
                                      __nv_bfloat16* __restrict__ Wl) {
    if (blockIdx.x == 63 && threadIdx.x == 0) {
        unsigned acc = 0;
        for (int i = 0; i < 64; i++) acc |= ei_raw[2 * i + 1];
        g_idx64 = (acc == 0u) ? 1 : 0;
    }
    __shared__ float s[4];
    if (threadIdx.x < 4) s[threadIdx.x] = 2.0f / (1.0f + expf(-logits[threadIdx.x]));
    __syncthreads();
    for (int idx = blockIdx.x * blockDim.x + threadIdx.x; idx < DF * DF;
         idx += gridDim.x * blockDim.x) {
        float vals[3];
        vals[0] = s[0] * Wself[idx] + s[2] * Whp[idx];
        vals[1] = s[1] * Wnb1[idx] - s[2] * Whp[idx];
        vals[2] = s[3] * Wnb2[idx];
        for (int ch = 0; ch < 3; ch++) {
            float v = vals[ch];
            __nv_bfloat16 hi = __float2bfloat16_rn(v);
            __nv_bfloat16 lo = __float2bfloat16_rn(v - __bfloat162float(hi));
            Wh[ch * 16384 + idx] = hi;
            Wl[ch * 16384 + idx] = lo;
        }
    }
}

// ---------------------------------------------------------------------------
// CSR build from deg (deg IS the clamped in-degree histogram -> no hist pass).
// Three-phase parallel scan (measured ~13 us total; chained version regressed).
// ---------------------------------------------------------------------------
__global__ void scan_a_kernel(const float* __restrict__ deg, int* __restrict__ scan,
                              int* __restrict__ bsum, int n) {
    __shared__ int sh[SCAN_B];
    int tid = threadIdx.x;
    int i = blockIdx.x * SCAN_B + tid;
    sh[tid] = (i < n) ? (int)deg[i] : 0;
    __syncthreads();
    for (int o = 1; o < SCAN_B; o <<= 1) {
        int t = (tid >= o) ? sh[tid - o] : 0;
        __syncthreads();
        if (tid >= o) sh[tid] += t;
        __syncthreads();
    }
    if (i < n) scan[i] = sh[tid];
    if (tid == SCAN_B - 1) bsum[blockIdx.x] = sh[tid];
}

__global__ void scan_b_kernel(int* __restrict__ bsum, int nb) {
    __shared__ int sh[1024];
    int tid = threadIdx.x;
    int v = (tid < nb) ? bsum[tid] : 0;
    sh[tid] = v;
    __syncthreads();
    for (int o = 1; o < 1024; o <<= 1) {
        int t = (tid >= o) ? sh[tid - o] : 0;
        __syncthreads();
        if (tid >= o) sh[tid] += t;
        __syncthreads();
    }
    if (tid < nb) bsum[tid] = sh[tid] - v;
}

__global__ void scan_c_kernel(const int* __restrict__ scan,
                              const int* __restrict__ bsum,
                              const float* __restrict__ deg,
                              int* __restrict__ rowptr, int* __restrict__ cur, int n) {
    int i = blockIdx.x * blockDim.x + threadIdx.x;
    if (i < n) {
        int incl = scan[i] + bsum[i / SCAN_B];
        int base = incl - (int)deg[i];
        rowptr[i] = base;
        cur[i] = base;
    }
}

__global__ void fill_kernel(const int* __restrict__ ei32,
                            int* __restrict__ cur, int* __restrict__ esrc,
                            long long E) {
    long long e = (long long)blockIdx.x * blockDim.x + threadIdx.x;
    if (e >= E) return;
    int idx64 = g_idx64;
    int src = load_idx(ei32, e, idx64);
    int dst = load_idx(ei32, e + E, idx64);
    int pos = atomicAdd(&cur[dst], 1);
    esrc[pos] = src;
}

// ---------------------------------------------------------------------------
// Gather-based mean aggregation: warp per node, lane owns one float4.
// Range = [rowptr[w], cur[w]) : cur is the post-fill cursor (= base + count).
// ---------------------------------------------------------------------------
__global__ __launch_bounds__(256) void agg_gather_kernel(
    const int* __restrict__ rowptr, const int* __restrict__ rowend,
    const int* __restrict__ esrc,
    const float4* __restrict__ x4, float4* __restrict__ out4,
    const float* __restrict__ deg, int Nn) {
    int w = (blockIdx.x * blockDim.x + threadIdx.x) >> 5;
    if (w >= Nn) return;
    int lane = threadIdx.x & 31;
    int s = rowptr[w];
    int t = rowend[w];
    float4 a = make_float4(0.f, 0.f, 0.f, 0.f);
    int j = s;
    for (; j + 8 <= t; j += 8) {
        int si[8];
#pragma unroll
        for (int u = 0; u < 8; u++) si[u] = esrc[j + u];
        float4 v[8];
#pragma unroll
        for (int u = 0; u < 8; u++) v[u] = x4[(long long)si[u] * 32 + lane];
        float4 p0, p1;
        p0.x = (v[0].x + v[1].x) + (v[2].x + v[3].x);
        p0.y = (v[0].y + v[1].y) + (v[2].y + v[3].y);
        p0.z = (v[0].z + v[1].z) + (v[2].z + v[3].z);
        p0.w = (v[0].w + v[1].w) + (v[2].w + v[3].w);
        p1.x = (v[4].x + v[5].x) + (v[6].x + v[7].x);
        p1.y = (v[4].y + v[5].y) + (v[6].y + v[7].y);
        p1.z = (v[4].z + v[5].z) + (v[6].z + v[7].z);
        p1.w = (v[4].w + v[5].w) + (v[6].w + v[7].w);
        a.x += p0.x + p1.x;
        a.y += p0.y + p1.y;
        a.z += p0.z + p1.z;
        a.w += p0.w + p1.w;
    }
    for (; j < t; j++) {
        int s0 = esrc[j];
        float4 v = x4[(long long)s0 * 32 + lane];
        a.x += v.x;
        a.y += v.y;
        a.z += v.z;
        a.w += v.w;
    }
    float rd = 1.0f / deg[w];
    a.x *= rd;
    a.y *= rd;
    a.z *= rd;
    a.w *= rd;
    out4[(long long)w * 32 + lane] = a;
}

// ---------------------------------------------------------------------------
// WMMA GEMM (CTA: 64 rows x 128 cols, K=384 as 3 chunks of 128) + bias + LN.
// 3-term bf16 split: Xh*Wh + Xh*Wl + Xl*Wh, fp32 accumulators.
// 8 warps; warp tile 64x16 (4x1 of 16x16 fragments) -> each warp owns a
// DISTINCT 16-col stripe, so global B-fragment loads are non-redundant:
// 16 frag loads/warp/chunk (vs 32 with the 32x64 tiling). A fragments come
// from smem (ldmatrix, cheap). smem = 36,864 B -> 2 CTAs/SM.
// ---------------------------------------------------------------------------
#define BMR 64    // CTA rows
#define LDX 144   // bf16 elements per row in X stage (288B rows, 32B aligned)
#define LDZ 132   // floats per row in Z epilogue tile

__global__ __launch_bounds__(256) void wmma_gemm_ln_kernel(
    const float* __restrict__ h, const float* __restrict__ nb1,
    const float* __restrict__ nb2,
    const __nv_bfloat16* __restrict__ Wh,
    const __nv_bfloat16* __restrict__ Wl,
    const float* __restrict__ bias, const float* __restrict__ gamma,
    const float* __restrict__ beta, float* __restrict__ out, int Nn) {
    extern __shared__ __align__(32) char sm[];
    __nv_bfloat16* Xh_s = (__nv_bfloat16*)sm;                 // 64*144*2 = 18,432
    __nv_bfloat16* Xl_s = (__nv_bfloat16*)(sm + 18432);       // 18,432 (total 36,864)
    float* Z = (float*)sm;                                    // 64*132*4 (aliases X)

    __shared__ float bias_s[128];
    __shared__ float gamma_s[128];
    __shared__ float beta_s[128];
    __shared__ float mean_s[BMR];
    __shared__ float inv_s[BMR];

    int tid = threadIdx.x;
    int wid = tid >> 5;
    int row0 = blockIdx.x * BMR;
    int wcol = wid * 16;            // this warp's 16-column stripe

    if (tid < 128) {
        bias_s[tid] = bias[tid];
        gamma_s[tid] = gamma[tid];
        beta_s[tid] = beta[tid];
    }

    wmma::fragment<wmma::accumulator, 16, 16, 16, float> acc[4];
    for (int i = 0; i < 4; i++)
        wmma::fill_fragment(acc[i], 0.0f);

    const float* srcs[3];
    srcs[0] = h;
    srcs[1] = nb1;
    srcs[2] = nb2;

    for (int ch = 0; ch < 3; ch++) {
        const float* S = srcs[ch];
        const __nv_bfloat16* WhC = Wh + ch * 16384;
        const __nv_bfloat16* WlC = Wl + ch * 16384;
        __syncthreads();   // previous chunk's consumers done before overwrite

        // Stage X: 64 rows x 128 cols fp32 -> bf16 hi/lo (2048 float4 loads).
        for (int it = 0; it < 8; it++) {
            int idx = it * 256 + tid;
            int row = idx >> 5;
            int col = (idx & 31) * 4;
            float4 v = make_float4(0.f, 0.f, 0.f, 0.f);
            int gr = row0 + row;
            if (gr < Nn) v = *(const float4*)(S + (long long)gr * DF + col);
            __nv_bfloat16 hx = __float2bfloat16_rn(v.x);
            __nv_bfloat16 hy = __float2bfloat16_rn(v.y);
            __nv_bfloat16 hz = __float2bfloat16_rn(v.z);
            __nv_bfloat16 hw = __float2bfloat16_rn(v.w);
            __nv_bfloat16 lx = __float2bfloat16_rn(v.x - __bfloat162float(hx));
            __nv_bfloat16 ly = __float2bfloat16_rn(v.y - __bfloat162float(hy));
            __nv_bfloat16 lz = __float2bfloat16_rn(v.z - __bfloat162float(hz));
            __nv_bfloat16 lw = __float2bfloat16_rn(v.w - __bfloat162float(hw));
            uint2 hv;
            uint2 lv;
            hv.x = (unsigned)__bfloat16_as_ushort(hx)
                 | ((unsigned)__bfloat16_as_ushort(hy) << 16);
            hv.y = (unsigned)__bfloat16_as_ushort(hz)
                 | ((unsigned)__bfloat16_as_ushort(hw) << 16);
            lv.x = (unsigned)__bfloat16_as_ushort(lx)
                 | ((unsigned)__bfloat16_as_ushort(ly) << 16);
            lv.y = (unsigned)__bfloat16_as_ushort(lz)
                 | ((unsigned)__bfloat16_as_ushort(lw) << 16);
            *(uint2*)(Xh_s + row * LDX + col) = hv;
            *(uint2*)(Xl_s + row * LDX + col) = lv;
        }
        __syncthreads();

        // MMA over this chunk's K=128. One B (hi,lo) pair per kstep per warp.
        for (int ks = 0; ks < 8; ks++) {
            int k0 = ks * 16;
            wmma::fragment<wmma::matrix_b, 16, 16, 16, __nv_bfloat16, wmma::col_major> bh, bl;
            wmma::load_matrix_sync(bh, WhC + wcol * 128 + k0, 128);
            wmma::load_matrix_sync(bl, WlC + wcol * 128 + k0, 128);
            for (int i = 0; i < 4; i++) {
                int r = i * 16;
                wmma::fragment<wmma::matrix_a, 16, 16, 16, __nv_bfloat16, wmma::row_major> ah, al;
                wmma::load_matrix_sync(ah, Xh_s + r * LDX + k0, LDX);
                wmma::load_matrix_sync(al, Xl_s + r * LDX + k0, LDX);
                wmma::mma_sync(acc[i], ah, bh, acc[i]);
                wmma::mma_sync(acc[i], ah, bl, acc[i]);
                wmma::mma_sync(acc[i], al, bh, acc[i]);
            }
        }
    }
    __syncthreads();   // all MMA consumers done; Z aliases X stage

    // Store accumulators to Z
    for (int i = 0; i < 4; i++) {
        wmma::store_matrix_sync(Z + (i * 16) * LDZ + wcol, acc[i], LDZ,
                                wmma::mem_row_major);
    }
    __syncthreads();

    // LayerNorm stats: 4 threads per row, 32 cols each; add bias in-place.
    {
        int row = tid >> 2;
        int q = tid & 3;
        float sum = 0.f;
        float sq = 0.f;
        for (int c = 0; c < 32; c++) {
            int col = q * 32 + c;
            float z = Z[row * LDZ + col] + bias_s[col];
            Z[row * LDZ + col] = z;
            sum += z;
            sq += z * z;
        }
        sum += __shfl_xor_sync(0xffffffffu, sum, 1);
        sq += __shfl_xor_sync(0xffffffffu, sq, 1);
        sum += __shfl_xor_sync(0xffffffffu, sum, 2);
        sq += __shfl_xor_sync(0xffffffffu, sq, 2);
        if (q == 0) {
            float mean = sum * (1.0f / 128.0f);
            float var = sq * (1.0f / 128.0f) - mean * mean;
            mean_s[row] = mean;
            inv_s[row] = rsqrtf(var + 1e-5f);
        }
    }
    __syncthreads();

    // Coalesced normalize + store: 8 iters x 256 threads x float4
    for (int it = 0; it < 8; it++) {
        int g = it * 1024 + tid * 4;
        int row = g >> 7;
        int col = g & 127;
        int gr = row0 + row;
        if (gr < Nn) {
            float m = mean_s[row];
            float iv = inv_s[row];
            float4 o;
            o.x = (Z[row * LDZ + col + 0] - m) * iv * gamma_s[col + 0] + beta_s[col + 0];
            o.y = (Z[row * LDZ + col + 1] - m) * iv * gamma_s[col + 1] + beta_s[col + 1];
            o.z = (Z[row * LDZ + col + 2] - m) * iv * gamma_s[col + 2] + beta_s[col + 2];
            o.w = (Z[row * LDZ + col + 3] - m) * iv * gamma_s[col + 3] + beta_s[col + 3];
            *(float4*)(out + (long long)gr * DF + col) = o;
        }
    }
}

// ---------------------------------------------------------------------------
// Launch
// ---------------------------------------------------------------------------
extern "C" void kernel_launch(void* const* d_in, const int* in_sizes, int n_in,
                              void* d_out, int out_size) {
    const float* h      = (const float*)d_in[0];
    const int*   ei32   = (const int*)d_in[1];
    const float* deg    = (const float*)d_in[2];
    const float* Wself  = (const float*)d_in[3];
    const float* Wnb1   = (const float*)d_in[4];
    const float* Whp    = (const float*)d_in[5];
    const float* Wnb2   = (const float*)d_in[6];
    const float* bias   = (const float*)d_in[7];
    const float* logits = (const float*)d_in[8];
    const float* gamma  = (const float*)d_in[9];
    const float* beta   = (const float*)d_in[10];
    float*       out    = (float*)d_out;

    int Nn = in_sizes[2];
    long long E = in_sizes[1] / 2;

    float* agg1;
    float* agg2;
    __nv_bfloat16* Wh;
    __nv_bfloat16* Wl;
    int* cur;
    int* scan;
    int* bsum;
    int* rowptr;
    int* esrc;
    cudaGetSymbolAddress((void**)&agg1, g_agg1);
    cudaGetSymbolAddress((void**)&agg2, g_agg2);
    cudaGetSymbolAddress((void**)&Wh, g_Wh);
    cudaGetSymbolAddress((void**)&Wl, g_Wl);
    cudaGetSymbolAddress((void**)&cur, g_cur);
    cudaGetSymbolAddress((void**)&scan, g_scan);
    cudaGetSymbolAddress((void**)&bsum, g_bsum);
    cudaGetSymbolAddress((void**)&rowptr, g_rowptr);
    cudaGetSymbolAddress((void**)&esrc, g_esrc);

    const int T = 256;
    int nb_nodes = (Nn + T - 1) / T;
    int nb_edges = (int)((E + T - 1) / T);
    int nb_scan  = (Nn + SCAN_B - 1) / SCAN_B;
    int nb_agg   = (Nn * 32 + T - 1) / T;
    int fb       = (Nn + BMR - 1) / BMR;
    const int GEMM_SMEM = 36864;   // Xh + Xl stage (Z epilogue aliases it)

    cudaFuncSetAttribute(wmma_gemm_ln_kernel,
                         cudaFuncAttributeMaxDynamicSharedMemorySize, GEMM_SMEM);

    // 1) weights + index-dtype detect (one kernel; completes before fill)
    weight_combine_kernel<<<64, T>>>(Wself, Wnb1, Whp, Wnb2, logits,
                                     (const unsigned*)ei32, Wh, Wl);
    // 2) CSR row bases from deg (three-phase parallel scan)
    scan_a_kernel<<<nb_scan, SCAN_B>>>(deg, scan, bsum, Nn);
    scan_b_kernel<<<1, 1024>>>(bsum, nb_scan);
    scan_c_kernel<<<nb_nodes, T>>>(scan, bsum, deg, rowptr, cur, Nn);
    // 3) adjacency fill (cursor ends at row base + count)
    fill_kernel<<<nb_edges, T>>>(ei32, cur, esrc, E);
    // 4) nb1 = mean-gather(h); nb2 = mean-gather(nb1)
    agg_gather_kernel<<<nb_agg, T>>>(rowptr, cur, esrc, (const float4*)h,
                                     (float4*)agg1, deg, Nn);
    agg_gather_kernel<<<nb_agg, T>>>(rowptr, cur, esrc, (const float4*)agg1,
                                     (float4*)agg2, deg, Nn);
    // 5) fused GEMM + bias + LayerNorm
    wmma_gemm_ln_kernel<<<fb, 256, GEMM_SMEM>>>(h, agg1, agg2, Wh, Wl,
                                                bias, gamma, beta, out, Nn);
}

// round 17
// speedup vs baseline: 1.3900x; 1.0320x over previous
#include <cuda_runtime.h>
#include <cuda_bf16.h>
#include <math.h>

#define NMAX 100000
#define ESLOTS 1700000   // E + N slack (deg-derived counts over-allocate empty rows)
#define DF   128
#define SCAN_B 1024

// Scratch (__device__ globals; allocation is forbidden).
__device__ float g_agg1[(size_t)NMAX * DF];
__device__ float g_agg2[(size_t)NMAX * DF];
__device__ __align__(16) __nv_bfloat16 g_Wh[3 * 16384];  // row-major [ch][j][k] hi
__device__ __align__(16) __nv_bfloat16 g_Wl[3 * 16384];  // row-major [ch][j][k] lo
__device__ int   g_idx64;
__device__ int   g_cur[NMAX];        // fill cursor (starts at row base)
__device__ int   g_scan[NMAX];
__device__ int   g_bsum[1024];
__device__ int   g_rowptr[NMAX];     // row base (from deg scan)
__device__ int   g_esrc[ESLOTS];

__device__ __forceinline__ int load_idx(const int* __restrict__ ei32,
                                        long long pos, int idx64) {
    return idx64 ? ei32[2 * pos] : ei32[pos];
}

__device__ __forceinline__ unsigned smem_u32(const void* p) {
    return (unsigned)__cvta_generic_to_shared(p);
}

// ldmatrix.x4: four 8x8 b16 tiles -> m16n8k16 A fragment (a0..a3)
__device__ __forceinline__ void ldmatrix_x4(unsigned* r, unsigned addr) {
    asm volatile("ldmatrix.sync.aligned.m8n8.x4.shared.b16 {%0,%1,%2,%3}, [%4];"
                 : "=r"(r[0]), "=r"(r[1]), "=r"(r[2]), "=r"(r[3]) : "r"(addr));
}

// mma m16n8k16 row.col f32 += bf16 x bf16
__device__ __forceinline__ void mma16816(float* c, const unsigned* a,
                                         const unsigned* b) {
    asm volatile(
        "mma.sync.aligned.m16n8k16.row.col.f32.bf16.bf16.f32 "
        "{%0,%1,%2,%3}, {%4,%5,%6,%7}, {%8,%9}, {%0,%1,%2,%3};"
        : "+f"(c[0]), "+f"(c[1]), "+f"(c[2]), "+f"(c[3])
        : "r"(a[0]), "r"(a[1]), "r"(a[2]), "r"(a[3]), "r"(b[0]), "r"(b[1]));
}

// ---------------------------------------------------------------------------
// Weights -> bf16 hi/lo, row-major [ch][j][k]. Block 63 also detects the
// edge-index dtype (int64 little-endian has zero odd words for v < 2^31).
// ch0: A = s0*W_self + s2*W_hp ; ch1: B = s1*W_nb1 - s2*W_hp ; ch2: C = s3*W_nb2
// ---------------------------------------------------------------------------
__global__ void weight_combine_kernel(const float* __restrict__ Wself,
                                      const float* __restrict__ Wnb1,
                                      const float* __restrict__ Whp,
                                      const float* __restrict__ Wnb2,
                                      const float* __restrict__ logits,
                                      const unsigned* __restrict__ ei_raw,
                                      __nv_bfloat16* __restrict__ Wh,
                                      __nv_bfloat16* __restrict__ Wl) {
    if (blockIdx.x == 63 && threadIdx.x == 0) {
        unsigned acc = 0;
        for (int i = 0; i < 64; i++) acc |= ei_raw[2 * i + 1];
        g_idx64 = (acc == 0u) ? 1 : 0;
    }
    __shared__ float s[4];
    if (threadIdx.x < 4) s[threadIdx.x] = 2.0f / (1.0f + expf(-logits[threadIdx.x]));
    __syncthreads();
    for (int idx = blockIdx.x * blockDim.x + threadIdx.x; idx < DF * DF;
         idx += gridDim.x * blockDim.x) {
        float vals[3];
        vals[0] = s[0] * Wself[idx] + s[2] * Whp[idx];
        vals[1] = s[1] * Wnb1[idx] - s[2] * Whp[idx];
        vals[2] = s[3] * Wnb2[idx];
        for (int ch = 0; ch < 3; ch++) {
            float v = vals[ch];
            __nv_bfloat16 hi = __float2bfloat16_rn(v);
            __nv_bfloat16 lo = __float2bfloat16_rn(v - __bfloat162float(hi));
            Wh[ch * 16384 + idx] = hi;
            Wl[ch * 16384 + idx] = lo;
        }
    }
}

// ---------------------------------------------------------------------------
// CSR build from deg (deg IS the clamped in-degree histogram -> no hist pass).
// ---------------------------------------------------------------------------
__global__ void scan_a_kernel(const float* __restrict__ deg, int* __restrict__ scan,
                              int* __restrict__ bsum, int n) {
    __shared__ int sh[SCAN_B];
    int tid = threadIdx.x;
    int i = blockIdx.x * SCAN_B + tid;
    sh[tid] = (i < n) ? (int)deg[i] : 0;
    __syncthreads();
    for (int o = 1; o < SCAN_B; o <<= 1) {
        int t = (tid >= o) ? sh[tid - o] : 0;
        __syncthreads();
        if (tid >= o) sh[tid] += t;
        __syncthreads();
    }
    if (i < n) scan[i] = sh[tid];
    if (tid == SCAN_B - 1) bsum[blockIdx.x] = sh[tid];
}

__global__ void scan_b_kernel(int* __restrict__ bsum, int nb) {
    __shared__ int sh[1024];
    int tid = threadIdx.x;
    int v = (tid < nb) ? bsum[tid] : 0;
    sh[tid] = v;
    __syncthreads();
    for (int o = 1; o < 1024; o <<= 1) {
        int t = (tid >= o) ? sh[tid - o] : 0;
        __syncthreads();
        if (tid >= o) sh[tid] += t;
        __syncthreads();
    }
    if (tid < nb) bsum[tid] = sh[tid] - v;
}

__global__ void scan_c_kernel(const int* __restrict__ scan,
                              const int* __restrict__ bsum,
                              const float* __restrict__ deg,
                              int* __restrict__ rowptr, int* __restrict__ cur, int n) {
    int i = blockIdx.x * blockDim.x + threadIdx.x;
    if (i < n) {
        int incl = scan[i] + bsum[i / SCAN_B];
        int base = incl - (int)deg[i];
        rowptr[i] = base;
        cur[i] = base;
    }
}

__global__ void fill_kernel(const int* __restrict__ ei32,
                            int* __restrict__ cur, int* __restrict__ esrc,
                            long long E) {
    long long e = (long long)blockIdx.x * blockDim.x + threadIdx.x;
    if (e >= E) return;
    int idx64 = g_idx64;
    int src = load_idx(ei32, e, idx64);
    int dst = load_idx(ei32, e + E, idx64);
    int pos = atomicAdd(&cur[dst], 1);
    esrc[pos] = src;
}

// ---------------------------------------------------------------------------
// Gather-based mean aggregation: warp per node, lane owns one float4.
// ---------------------------------------------------------------------------
__global__ __launch_bounds__(256) void agg_gather_kernel(
    const int* __restrict__ rowptr, const int* __restrict__ rowend,
    const int* __restrict__ esrc,
    const float4* __restrict__ x4, float4* __restrict__ out4,
    const float* __restrict__ deg, int Nn) {
    int w = (blockIdx.x * blockDim.x + threadIdx.x) >> 5;
    if (w >= Nn) return;
    int lane = threadIdx.x & 31;
    int s = rowptr[w];
    int t = rowend[w];
    float4 a = make_float4(0.f, 0.f, 0.f, 0.f);
    int j = s;
    for (; j + 8 <= t; j += 8) {
        int si[8];
#pragma unroll
        for (int u = 0; u < 8; u++) si[u] = esrc[j + u];
        float4 v[8];
#pragma unroll
        for (int u = 0; u < 8; u++) v[u] = x4[(long long)si[u] * 32 + lane];
        float4 p0, p1;
        p0.x = (v[0].x + v[1].x) + (v[2].x + v[3].x);
        p0.y = (v[0].y + v[1].y) + (v[2].y + v[3].y);
        p0.z = (v[0].z + v[1].z) + (v[2].z + v[3].z);
        p0.w = (v[0].w + v[1].w) + (v[2].w + v[3].w);
        p1.x = (v[4].x + v[5].x) + (v[6].x + v[7].x);
        p1.y = (v[4].y + v[5].y) + (v[6].y + v[7].y);
        p1.z = (v[4].z + v[5].z) + (v[6].z + v[7].z);
        p1.w = (v[4].w + v[5].w) + (v[6].w + v[7].w);
        a.x += p0.x + p1.x;
        a.y += p0.y + p1.y;
        a.z += p0.z + p1.z;
        a.w += p0.w + p1.w;
    }
    for (; j < t; j++) {
        int s0 = esrc[j];
        float4 v = x4[(long long)s0 * 32 + lane];
        a.x += v.x;
        a.y += v.y;
        a.z += v.z;
        a.w += v.w;
    }
    float rd = 1.0f / deg[w];
    a.x *= rd;
    a.y *= rd;
    a.z *= rd;
    a.w *= rd;
    out4[(long long)w * 32 + lane] = a;
}

// ---------------------------------------------------------------------------
// Raw-MMA GEMM (CTA: 64 rows x 128 cols, K=384 as 3 chunks of 128) + bias+LN.
// mma.sync.m16n8k16 bf16, 3-term split: Xh*Wh + Xh*Wl + Xl*Wh, fp32 acc.
// 8 warps, warp stripe = 16 cols (2 n8 slices), 4 m16 row tiles.
// A via ldmatrix.x4 from smem (1 instr per 16x16 frag vs 128 scalar LDS);
// B frags are contiguous k-pairs in row-major W -> one LDG.32 per reg.
// smem = 34,816 B -> 2 CTAs/SM.
// ---------------------------------------------------------------------------
#define BMR 64    // CTA rows
#define LDX 136   // bf16 per row in X stage (272B rows, 16B-aligned; LDSM conflict-free)
#define LDZ 132   // floats per row in Z epilogue tile

__global__ __launch_bounds__(256) void mma_gemm_ln_kernel(
    const float* __restrict__ h, const float* __restrict__ nb1,
    const float* __restrict__ nb2,
    const __nv_bfloat16* __restrict__ Wh,
    const __nv_bfloat16* __restrict__ Wl,
    const float* __restrict__ bias, const float* __restrict__ gamma,
    const float* __restrict__ beta, float* __restrict__ out, int Nn) {
    extern __shared__ __align__(32) char sm[];
    __nv_bfloat16* Xh_s = (__nv_bfloat16*)sm;                 // 64*136*2 = 17,408
    __nv_bfloat16* Xl_s = (__nv_bfloat16*)(sm + 17408);       // 17,408 (total 34,816)
    float* Z = (float*)sm;                                    // 64*132*4 (aliases X)

    __shared__ float bias_s[128];
    __shared__ float gamma_s[128];
    __shared__ float beta_s[128];
    __shared__ float mean_s[BMR];
    __shared__ float inv_s[BMR];

    int tid = threadIdx.x;
    int wid = tid >> 5;
    int lane = tid & 31;
    int row0 = blockIdx.x * BMR;
    int wcol = wid * 16;            // this warp's 16-column stripe

    if (tid < 128) {
        bias_s[tid] = bias[tid];
        gamma_s[tid] = gamma[tid];
        beta_s[tid] = beta[tid];
    }

    float acc[4][2][4];             // [m16 tile][n8 slice][regs]
#pragma unroll
    for (int i = 0; i < 4; i++)
#pragma unroll
        for (int j = 0; j < 2; j++)
#pragma unroll
            for (int r = 0; r < 4; r++) acc[i][j][r] = 0.f;

    const float* srcs[3];
    srcs[0] = h;
    srcs[1] = nb1;
    srcs[2] = nb2;

    unsigned xh_u = smem_u32(Xh_s);
    unsigned xl_u = smem_u32(Xl_s);
    // ldmatrix per-lane address offset within a 16x16 tile:
    // lane 0-15 -> rows 0-15 (first 8 cols), lane 16-31 -> rows 0-15 (cols 8-15)
    unsigned lm_off = (unsigned)((lane & 15) * LDX + ((lane >> 4) << 3)) * 2u;
    // B per-thread coords for m16n8k16 col-major frag
    int bn = lane >> 2;             // n within 8-col slice
    int bk = (lane & 3) * 2;        // k pair base

    for (int ch = 0; ch < 3; ch++) {
        const float* S = srcs[ch];
        const __nv_bfloat16* WhC = Wh + ch * 16384;
        const __nv_bfloat16* WlC = Wl + ch * 16384;
        __syncthreads();   // previous chunk's consumers done before overwrite

        // Stage X: 64 rows x 128 cols fp32 -> bf16 hi/lo (2048 float4 loads).
        for (int it = 0; it < 8; it++) {
            int idx = it * 256 + tid;
            int row = idx >> 5;
            int col = (idx & 31) * 4;
            float4 v = make_float4(0.f, 0.f, 0.f, 0.f);
            int gr = row0 + row;
            if (gr < Nn) v = *(const float4*)(S + (long long)gr * DF + col);
            __nv_bfloat16 hx = __float2bfloat16_rn(v.x);
            __nv_bfloat16 hy = __float2bfloat16_rn(v.y);
            __nv_bfloat16 hz = __float2bfloat16_rn(v.z);
            __nv_bfloat16 hw = __float2bfloat16_rn(v.w);
            __nv_bfloat16 lx = __float2bfloat16_rn(v.x - __bfloat162float(hx));
            __nv_bfloat16 ly = __float2bfloat16_rn(v.y - __bfloat162float(hy));
            __nv_bfloat16 lz = __float2bfloat16_rn(v.z - __bfloat162float(hz));
            __nv_bfloat16 lw = __float2bfloat16_rn(v.w - __bfloat162float(hw));
            uint2 hv;
            uint2 lv;
            hv.x = (unsigned)__bfloat16_as_ushort(hx)
                 | ((unsigned)__bfloat16_as_ushort(hy) << 16);
            hv.y = (unsigned)__bfloat16_as_ushort(hz)
                 | ((unsigned)__bfloat16_as_ushort(hw) << 16);
            lv.x = (unsigned)__bfloat16_as_ushort(lx)
                 | ((unsigned)__bfloat16_as_ushort(ly) << 16);
            lv.y = (unsigned)__bfloat16_as_ushort(lz)
                 | ((unsigned)__bfloat16_as_ushort(lw) << 16);
            *(uint2*)(Xh_s + row * LDX + col) = hv;
            *(uint2*)(Xl_s + row * LDX + col) = lv;
        }
        __syncthreads();

        // MMA over this chunk's K=128.
#pragma unroll
        for (int ks = 0; ks < 8; ks++) {
            int k0 = ks * 16;
            // B fragments: [j][h/l][2 regs], each reg one aligned LDG.32
            unsigned bh[2][2], bl[2][2];
#pragma unroll
            for (int j = 0; j < 2; j++) {
                const __nv_bfloat16* ph = WhC + (wcol + j * 8 + bn) * 128 + k0 + bk;
                const __nv_bfloat16* pl = WlC + (wcol + j * 8 + bn) * 128 + k0 + bk;
                bh[j][0] = *(const unsigned*)ph;
                bh[j][1] = *(const unsigned*)(ph + 8);
                bl[j][0] = *(const unsigned*)pl;
                bl[j][1] = *(const unsigned*)(pl + 8);
            }
#pragma unroll
            for (int i = 0; i < 4; i++) {
                unsigned ah[4], al[4];
                unsigned tile_off = (unsigned)(i * 16 * LDX + k0) * 2u + lm_off;
                ldmatrix_x4(ah, xh_u + tile_off);
                ldmatrix_x4(al, xl_u + tile_off);
#pragma unroll
                for (int j = 0; j < 2; j++) {
                    mma16816(acc[i][j], ah, bh[j]);
                    mma16816(acc[i][j], ah, bl[j]);
                    mma16816(acc[i][j], al, bh[j]);
                }
            }
        }
    }
    __syncthreads();   // all MMA consumers done; Z aliases X stage

    // Store accumulators to Z (c0,c1 contiguous cols; c2,c3 at row+8)
    {
        int cr = lane >> 2;
        int cc = (lane & 3) * 2;
#pragma unroll
        for (int i = 0; i < 4; i++) {
#pragma unroll
            for (int j = 0; j < 2; j++) {
                int r = i * 16 + cr;
                int c = wcol + j * 8 + cc;
                *(float2*)&Z[r * LDZ + c] = make_float2(acc[i][j][0], acc[i][j][1]);
                *(float2*)&Z[(r + 8) * LDZ + c] = make_float2(acc[i][j][2], acc[i][j][3]);
            }
        }
    }
    __syncthreads();

    // LayerNorm stats: 4 threads per row, 32 cols each; add bias in-place.
    {
        int row = tid >> 2;
        int q = tid & 3;
        float sum = 0.f;
        float sq = 0.f;
        for (int c = 0; c < 32; c++) {
            int col = q * 32 + c;
            float z = Z[row * LDZ + col] + bias_s[col];
            Z[row * LDZ + col] = z;
            sum += z;
            sq += z * z;
        }
        sum += __shfl_xor_sync(0xffffffffu, sum, 1);
        sq += __shfl_xor_sync(0xffffffffu, sq, 1);
        sum += __shfl_xor_sync(0xffffffffu, sum, 2);
        sq += __shfl_xor_sync(0xffffffffu, sq, 2);
        if (q == 0) {
            float mean = sum * (1.0f / 128.0f);
            float var = sq * (1.0f / 128.0f) - mean * mean;
            mean_s[row] = mean;
            inv_s[row] = rsqrtf(var + 1e-5f);
        }
    }
    __syncthreads();

    // Coalesced normalize + store: 8 iters x 256 threads x float4
    for (int it = 0; it < 8; it++) {
        int g = it * 1024 + tid * 4;
        int row = g >> 7;
        int col = g & 127;
        int gr = row0 + row;
        if (gr < Nn) {
            float m = mean_s[row];
            float iv = inv_s[row];
            float4 o;
            o.x = (Z[row * LDZ + col + 0] - m) * iv * gamma_s[col + 0] + beta_s[col + 0];
            o.y = (Z[row * LDZ + col + 1] - m) * iv * gamma_s[col + 1] + beta_s[col + 1];
            o.z = (Z[row * LDZ + col + 2] - m) * iv * gamma_s[col + 2] + beta_s[col + 2];
            o.w = (Z[row * LDZ + col + 3] - m) * iv * gamma_s[col + 3] + beta_s[col + 3];
            *(float4*)(out + (long long)gr * DF + col) = o;
        }
    }
}

// ---------------------------------------------------------------------------
// Launch
// ---------------------------------------------------------------------------
extern "C" void kernel_launch(void* const* d_in, const int* in_sizes, int n_in,
                              void* d_out, int out_size) {
    const float* h      = (const float*)d_in[0];
    const int*   ei32   = (const int*)d_in[1];
    const float* deg    = (const float*)d_in[2];
    const float* Wself  = (const float*)d_in[3];
    const float* Wnb1   = (const float*)d_in[4];
    const float* Whp    = (const float*)d_in[5];
    const float* Wnb2   = (const float*)d_in[6];
    const float* bias   = (const float*)d_in[7];
    const float* logits = (const float*)d_in[8];
    const float* gamma  = (const float*)d_in[9];
    const float* beta   = (const float*)d_in[10];
    float*       out    = (float*)d_out;

    int Nn = in_sizes[2];
    long long E = in_sizes[1] / 2;

    float* agg1;
    float* agg2;
    __nv_bfloat16* Wh;
    __nv_bfloat16* Wl;
    int* cur;
    int* scan;
    int* bsum;
    int* rowptr;
    int* esrc;
    cudaGetSymbolAddress((void**)&agg1, g_agg1);
    cudaGetSymbolAddress((void**)&agg2, g_agg2);
    cudaGetSymbolAddress((void**)&Wh, g_Wh);
    cudaGetSymbolAddress((void**)&Wl, g_Wl);
    cudaGetSymbolAddress((void**)&cur, g_cur);
    cudaGetSymbolAddress((void**)&scan, g_scan);
    cudaGetSymbolAddress((void**)&bsum, g_bsum);
    cudaGetSymbolAddress((void**)&rowptr, g_rowptr);
    cudaGetSymbolAddress((void**)&esrc, g_esrc);

    const int T = 256;
    int nb_nodes = (Nn + T - 1) / T;
    int nb_edges = (int)((E + T - 1) / T);
    int nb_scan  = (Nn + SCAN_B - 1) / SCAN_B;
    int nb_agg   = (Nn * 32 + T - 1) / T;
    int fb       = (Nn + BMR - 1) / BMR;
    const int GEMM_SMEM = 34816;   // Xh + Xl stage (Z epilogue aliases it)

    cudaFuncSetAttribute(mma_gemm_ln_kernel,
                         cudaFuncAttributeMaxDynamicSharedMemorySize, GEMM_SMEM);

    // 1) weights + index-dtype detect (one kernel; completes before fill)
    weight_combine_kernel<<<64, T>>>(Wself, Wnb1, Whp, Wnb2, logits,
                                     (const unsigned*)ei32, Wh, Wl);
    // 2) CSR row bases from deg (three-phase parallel scan)
    scan_a_kernel<<<nb_scan, SCAN_B>>>(deg, scan, bsum, Nn);
    scan_b_kernel<<<1, 1024>>>(bsum, nb_scan);
    scan_c_kernel<<<nb_nodes, T>>>(scan, bsum, deg, rowptr, cur, Nn);
    // 3) adjacency fill (cursor ends at row base + count)
    fill_kernel<<<nb_edges, T>>>(ei32, cur, esrc, E);
    // 4) nb1 = mean-gather(h); nb2 = mean-gather(nb1)
    agg_gather_kernel<<<nb_agg, T>>>(rowptr, cur, esrc, (const float4*)h,
                                     (float4*)agg1, deg, Nn);
    agg_gather_kernel<<<nb_agg, T>>>(rowptr, cur, esrc, (const float4*)agg1,
                                     (float4*)agg2, deg, Nn);
    // 5) fused GEMM + bias + LayerNorm (raw mma.sync + ldmatrix)
    mma_gemm_ln_kernel<<<fb, 256, GEMM_SMEM>>>(h, agg1, agg2, Wh, Wl,
                                               bias, gamma, beta, out, Nn);
}